// round 10
// baseline (speedup 1.0000x reference)
#include <cuda_runtime.h>
#include <cuda_fp16.h>
#include <math.h>

#define BB   2
#define CC   64
#define NPTS 20000
#define KK   16
#define CO   64
#define NODES (BB * NPTS)

// Scratch (device globals: allocation-free rule)
__device__ uint4 g_U[NODES * 8];      // (W1-W2) @ x   per node, fp16
__device__ uint4 g_V[NODES * 8];      // W2      @ x   per node, fp16
__device__ float g_posT[NODES * 4];   // pos transposed to [node][4]

__device__ __forceinline__ unsigned f2h2(float lo, float hi) {
    __half2 h = __floats2half2_rn(lo, hi);
    return *reinterpret_cast<unsigned*>(&h);
}
__device__ __forceinline__ __half2 u2h(unsigned x) {
    return *reinterpret_cast<__half2*>(&x);
}
__device__ __forceinline__ __half2 hmax2_xor(__half2 a, int m) {
    unsigned o = __shfl_xor_sync(0xFFFFFFFFu, *reinterpret_cast<unsigned*>(&a), m);
    return __hmax2(a, u2h(o));
}

// ---------------------------------------------------------------------------
// Kernel 1: per-node transform u = (W1-W2)x, v = W2 x, fused pos transpose
// and fused weight prep. tile0 selects the node range: this launch covers
// global node tiles [tile0, tile0 + gridDim.x), 64 nodes per tile.
// ---------------------------------------------------------------------------
__global__ __launch_bounds__(256) void uv_kernel(const float* __restrict__ x,
                                                 const float* __restrict__ pos,
                                                 const float* __restrict__ W,
                                                 int tile0) {
    __shared__ float sW[64 * 128];   // 32 KB (swizzled)
    __shared__ float sx[64 * 64];    // 16 KB

    int tid  = threadIdx.x;
    int base = (blockIdx.x + tile0) * 64;

    // --- Stage W (pass 1): coalesced float4 reads, swizzled transposed STS.
    {
        const float4* W4 = reinterpret_cast<const float4*>(W);  // 2048 quads
#pragma unroll
        for (int j = 0; j < 8; ++j) {
            int i4 = tid + j * 256;
            int o  = i4 >> 5;
            int c4 = i4 & 31;
            float4 w = W4[i4];
#pragma unroll
            for (int m = 0; m < 4; ++m) {
                int   c2  = c4 * 4 + m;
                float val = (&w.x)[m];
                int   c   = c2 & 63;
                int   oc  = (c2 < 64) ? o : (64 + o);
                int   sw  = ((c >> 2) & 7) << 2;
                sW[c * 128 + (oc ^ sw)] = val;
            }
        }
    }

    // --- Stage x tile: sx[c][nl] = x[b, c, n] (coalesced over nl).
#pragma unroll
    for (int j = 0; j < 16; ++j) {
        int i  = tid + j * 256;
        int c  = i >> 6, nl = i & 63;
        int node = base + nl;
        int b  = node / NPTS;
        int n  = node - b * NPTS;
        sx[c * 64 + nl] = x[b * CC * NPTS + c * NPTS + n];
    }

    // --- pos transpose by the first 64 threads.
    if (tid < 64) {
        int node = base + tid;
        int b = node / NPTS;
        int n = node - b * NPTS;
        const float* pb = pos + b * 3 * NPTS + n;
        float4 p;
        p.x = pb[0];
        p.y = pb[NPTS];
        p.z = pb[2 * NPTS];
        p.w = 0.0f;
        reinterpret_cast<float4*>(g_posT)[node] = p;
    }
    __syncthreads();

    // --- Pass 2: A -= B in the swizzled domain (B slot = A slot + 64).
#pragma unroll
    for (int a = tid; a < 4096; a += 256) {
        int c  = a >> 6;
        int oo = a & 63;
        sW[c * 128 + oo] -= sW[c * 128 + oo + 64];
    }
    __syncthreads();

    int og = tid >> 5;          // output group 0..7 (16 outputs each)
    int ng = tid & 31;          // node pair 0..31

    float a0[16], a1[16];
#pragma unroll
    for (int t = 0; t < 16; ++t) { a0[t] = 0.0f; a1[t] = 0.0f; }

    const float2* xcol = reinterpret_cast<const float2*>(sx) + ng;
    const float4* sW4  = reinterpret_cast<const float4*>(sW);
    const float4* pA   = sW4 + og * 4;
    const float4* pB   = sW4 + ((og * 4) ^ 4);

#pragma unroll
    for (int c = 0; c < 64; ++c) {
        float2 xx = xcol[c * 32];
        const int K  = (c >> 2) & 7;
        const float4* p = (K & 4) ? pB : pA;
        float4 w0 = p[c * 32 + (0 ^ (K & 3))];
        float4 w1 = p[c * 32 + (1 ^ (K & 3))];
        float4 w2 = p[c * 32 + (2 ^ (K & 3))];
        float4 w3 = p[c * 32 + (3 ^ (K & 3))];
        a0[0]  = fmaf(w0.x, xx.x, a0[0]);   a1[0]  = fmaf(w0.x, xx.y, a1[0]);
        a0[1]  = fmaf(w0.y, xx.x, a0[1]);   a1[1]  = fmaf(w0.y, xx.y, a1[1]);
        a0[2]  = fmaf(w0.z, xx.x, a0[2]);   a1[2]  = fmaf(w0.z, xx.y, a1[2]);
        a0[3]  = fmaf(w0.w, xx.x, a0[3]);   a1[3]  = fmaf(w0.w, xx.y, a1[3]);
        a0[4]  = fmaf(w1.x, xx.x, a0[4]);   a1[4]  = fmaf(w1.x, xx.y, a1[4]);
        a0[5]  = fmaf(w1.y, xx.x, a0[5]);   a1[5]  = fmaf(w1.y, xx.y, a1[5]);
        a0[6]  = fmaf(w1.z, xx.x, a0[6]);   a1[6]  = fmaf(w1.z, xx.y, a1[6]);
        a0[7]  = fmaf(w1.w, xx.x, a0[7]);   a1[7]  = fmaf(w1.w, xx.y, a1[7]);
        a0[8]  = fmaf(w2.x, xx.x, a0[8]);   a1[8]  = fmaf(w2.x, xx.y, a1[8]);
        a0[9]  = fmaf(w2.y, xx.x, a0[9]);   a1[9]  = fmaf(w2.y, xx.y, a1[9]);
        a0[10] = fmaf(w2.z, xx.x, a0[10]);  a1[10] = fmaf(w2.z, xx.y, a1[10]);
        a0[11] = fmaf(w2.w, xx.x, a0[11]);  a1[11] = fmaf(w2.w, xx.y, a1[11]);
        a0[12] = fmaf(w3.x, xx.x, a0[12]);  a1[12] = fmaf(w3.x, xx.y, a1[12]);
        a0[13] = fmaf(w3.y, xx.x, a0[13]);  a1[13] = fmaf(w3.y, xx.y, a1[13]);
        a0[14] = fmaf(w3.z, xx.x, a0[14]);  a1[14] = fmaf(w3.z, xx.y, a1[14]);
        a0[15] = fmaf(w3.w, xx.x, a0[15]);  a1[15] = fmaf(w3.w, xx.y, a1[15]);
    }

    // Convert to fp16 and store. og 0..3 -> U, og 4..7 -> V.
    int node0 = base + 2 * ng;
    uint4* dst = ((og < 4) ? g_U : g_V) + node0 * 8 + (og & 3) * 2;
    dst[0] = make_uint4(f2h2(a0[0],  a0[1]),  f2h2(a0[2],  a0[3]),
                        f2h2(a0[4],  a0[5]),  f2h2(a0[6],  a0[7]));
    dst[1] = make_uint4(f2h2(a0[8],  a0[9]),  f2h2(a0[10], a0[11]),
                        f2h2(a0[12], a0[13]), f2h2(a0[14], a0[15]));
    dst[8] = make_uint4(f2h2(a1[0],  a1[1]),  f2h2(a1[2],  a1[3]),
                        f2h2(a1[4],  a1[5]),  f2h2(a1[6],  a1[7]));
    dst[9] = make_uint4(f2h2(a1[8],  a1[9]),  f2h2(a1[10], a1[11]),
                        f2h2(a1[12], a1[13]), f2h2(a1[14], a1[15]));
}

// ---------------------------------------------------------------------------
// Kernel 2: per-edge combine + suppression + max over K, for ONE batch
// (b passed in so the two batches can run on different streams).
// ---------------------------------------------------------------------------
__global__ __launch_bounds__(256) void edge_kernel(const int* __restrict__ ei,
                                                   const float* __restrict__ bias,
                                                   float* __restrict__ out,
                                                   int b) {
    __shared__ float    sm[8 * 66];   // output staging
    __shared__ unsigned ssh[8 * 16];  // suppression as half2(s,s), per warp/k
    __shared__ int      si[8 * 32];   // [warp][0..15: i1 (center), 16..31: i0]
    __shared__ unsigned sbias[32];    // bias as 32 half2

    int tid  = threadIdx.x;
    int warp = tid >> 5;
    int lane = tid & 31;

    if (tid < 32) {
        float2 bf = reinterpret_cast<const float2*>(bias)[tid];
        sbias[tid] = f2h2(bf.x, bf.y);
    }

    int n = blockIdx.x * 8 + warp;   // point within batch b

    const int* e0 = ei + (b * NPTS + n) * KK;                    // neighbor idx
    const int* e1 = ei + (BB * NPTS * KK) + (b * NPTS + n) * KK; // center idx

    const uint4*  Ub = g_U + b * NPTS * 8;
    const uint4*  Vb = g_V + b * NPTS * 8;
    const float4* Pb = reinterpret_cast<const float4*>(g_posT) + b * NPTS;

    if (lane < KK) {
        int i0 = e0[lane];
        int i1 = e1[lane];
        si[warp * 32 + lane]      = i1;
        si[warp * 32 + 16 + lane] = i0;
        float4 p1 = Pb[i1];
        float4 p0 = Pb[i0];
        float dx = p1.x - p0.x, dy = p1.y - p0.y, dz = p1.z - p0.z;
        float dis = sqrtf(dx * dx + dy * dy + dz * dz);
        float s = 2.0f / (1.0f + __expf(dis));   // 2*sigmoid(-dis)
        ssh[warp * 16 + lane] = f2h2(s, s);
    }
    __syncthreads();

    int esub = lane >> 3;    // which of 4 edges this pass
    int q    = lane & 7;     // which 16B quad of the 128B row

    uint4    u[4], v[4];
    unsigned sh[4];
#pragma unroll
    for (int p = 0; p < 4; ++p) {
        int k  = p * 4 + esub;
        int i1 = si[warp * 32 + k];
        int i0 = si[warp * 32 + 16 + k];
        u[p]  = Ub[i1 * 8 + q];
        v[p]  = Vb[i0 * 8 + q];
        sh[p] = ssh[warp * 16 + k];
    }

    uint4 bq = reinterpret_cast<const uint4*>(sbias)[q];
    __half2 b0 = u2h(bq.x), b1 = u2h(bq.y), b2 = u2h(bq.z), b3 = u2h(bq.w);

    const __half2 z = __floats2half2_rn(0.0f, 0.0f);
    __half2 a0 = z, a1 = z, a2 = z, a3 = z;

#pragma unroll
    for (int p = 0; p < 4; ++p) {
        __half2 s2 = u2h(sh[p]);
        a0 = __hmax2(a0, __hmul2(__hmax2(__hadd2(__hadd2(u2h(u[p].x), u2h(v[p].x)), b0), z), s2));
        a1 = __hmax2(a1, __hmul2(__hmax2(__hadd2(__hadd2(u2h(u[p].y), u2h(v[p].y)), b1), z), s2));
        a2 = __hmax2(a2, __hmul2(__hmax2(__hadd2(__hadd2(u2h(u[p].z), u2h(v[p].z)), b2), z), s2));
        a3 = __hmax2(a3, __hmul2(__hmax2(__hadd2(__hadd2(u2h(u[p].w), u2h(v[p].w)), b3), z), s2));
    }

    a0 = hmax2_xor(a0, 8);  a1 = hmax2_xor(a1, 8);
    a2 = hmax2_xor(a2, 8);  a3 = hmax2_xor(a3, 8);
    a0 = hmax2_xor(a0, 16); a1 = hmax2_xor(a1, 16);
    a2 = hmax2_xor(a2, 16); a3 = hmax2_xor(a3, 16);

    if (esub == 0) {
        float2* dst = reinterpret_cast<float2*>(sm + warp * 66 + q * 8);
        dst[0] = __half22float2(a0);
        dst[1] = __half22float2(a1);
        dst[2] = __half22float2(a2);
        dst[3] = __half22float2(a3);
    }
    __syncthreads();

    int on = blockIdx.x * 8;
#pragma unroll
    for (int e = tid; e < CO * 8; e += 256) {
        int o  = e >> 3;
        int nn = e & 7;
        out[(b * CO + o) * NPTS + on + nn] = sm[nn * 66 + o];
    }
}

extern "C" void kernel_launch(void* const* d_in, const int* in_sizes, int n_in,
                              void* d_out, int out_size) {
    const float* x    = (const float*)d_in[0];
    const int*   ei   = (const int*)d_in[1];
    const float* pos  = (const float*)d_in[2];
    const float* W    = (const float*)d_in[3];
    const float* bias = (const float*)d_in[4];
    float* out = (float*)d_out;

    // Tile split: uvA covers tiles 0..312 (nodes 0..20031 — a superset of
    // batch 0), uvB covers tiles 313..624 (rest of batch 1).
    // Fork-join: edge(b=0) overlaps uvB + edge(b=1) on a side stream.
    // uv is FMA-bound, edge is L1/LSU-bound -> good co-residency.
    cudaStream_t s2 = 0;
    cudaEvent_t  eA = 0, eB = 0;
    bool forked =
        cudaStreamCreateWithFlags(&s2, cudaStreamNonBlocking) == cudaSuccess &&
        cudaEventCreateWithFlags(&eA, cudaEventDisableTiming) == cudaSuccess &&
        cudaEventCreateWithFlags(&eB, cudaEventDisableTiming) == cudaSuccess;

    if (forked) {
        uv_kernel<<<313, 256>>>(x, pos, W, 0);
        cudaEventRecord(eA, 0);
        cudaStreamWaitEvent(s2, eA, 0);
        uv_kernel<<<312, 256, 0, s2>>>(x, pos, W, 313);
        edge_kernel<<<NPTS / 8, 256>>>(ei, bias, out, 0);          // main
        edge_kernel<<<NPTS / 8, 256, 0, s2>>>(ei, bias, out, 1);   // side
        cudaEventRecord(eB, s2);
        cudaStreamWaitEvent(0, eB, 0);
        // Handles intentionally leaked: kernel_launch runs only 2-3 times
        // (correctness + capture); destroying capture-referenced handles
        // mid-capture is unsafe.
    } else {
        // Capture mode rejected stream/event creation: sequential fallback.
        cudaGetLastError();   // clear sticky error from the failed create
        uv_kernel<<<625, 256>>>(x, pos, W, 0);
        edge_kernel<<<NPTS / 8, 256>>>(ei, bias, out, 0);
        edge_kernel<<<NPTS / 8, 256>>>(ei, bias, out, 1);
    }
}

// round 11
// speedup vs baseline: 1.5697x; 1.5697x over previous
#include <cuda_runtime.h>
#include <cuda_fp16.h>
#include <math.h>

#define BB   2
#define CC   64
#define NPTS 20000
#define KK   16
#define CO   64
#define NODES (BB * NPTS)

// Scratch (device globals: allocation-free rule)
__device__ uint4 g_U[NODES * 8];      // (W1-W2) @ x   per node, fp16
__device__ uint4 g_V[NODES * 8];      // W2      @ x   per node, fp16
__device__ float g_posT[NODES * 4];   // pos transposed to [node][4]

__device__ __forceinline__ unsigned f2h2(float lo, float hi) {
    __half2 h = __floats2half2_rn(lo, hi);
    return *reinterpret_cast<unsigned*>(&h);
}
__device__ __forceinline__ __half2 u2h(unsigned x) {
    return *reinterpret_cast<__half2*>(&x);
}
__device__ __forceinline__ __half2 hmax2_xor(__half2 a, int m) {
    unsigned o = __shfl_xor_sync(0xFFFFFFFFu, *reinterpret_cast<unsigned*>(&a), m);
    return __hmax2(a, u2h(o));
}

__device__ __forceinline__ void mma_16x8x16(float d[4],
                                            unsigned a0, unsigned a1,
                                            unsigned a2, unsigned a3,
                                            unsigned b0, unsigned b1) {
    asm volatile(
        "mma.sync.aligned.m16n8k16.row.col.f32.f16.f16.f32 "
        "{%0,%1,%2,%3}, {%4,%5,%6,%7}, {%8,%9}, {%0,%1,%2,%3};"
        : "+f"(d[0]), "+f"(d[1]), "+f"(d[2]), "+f"(d[3])
        : "r"(a0), "r"(a1), "r"(a2), "r"(a3), "r"(b0), "r"(b1));
}

// ---------------------------------------------------------------------------
// Kernel 1: per-node transform via tensor-core mma (fp16 in, fp32 acc).
// Block = 256 threads = 64-node tile, 625 blocks (exact: 625*64 = 40000).
//   sx[node][c]  64x72 halves (pad 72: fragment LDS conflict-free)
//   sW[oc][c]   128x72 halves (oc<64: W1-W2, oc>=64: W2)
// Warp w: nodes m0 = (w&3)*16, outputs half_sel = w>>2 (0 -> U, 1 -> V).
// Per warp: 4 k-steps x 8 n-tiles of m16n8k16 = 32 mma.
// Fragment layout (PTX m16n8k16, g = lane>>2, t = lane&3):
//   A: a0=(g,2t..), a1=(g+8,2t..), a2=(g,2t+8..), a3=(g+8,2t+8..)
//   B (col-major k16n8, B[k][n] = sW[n][k]): b0 = sW[n=g][2t..], b1 = +8
//   C: c0,c1=(g, 2t/2t+1), c2,c3=(g+8, 2t/2t+1)
// ---------------------------------------------------------------------------
__global__ __launch_bounds__(256) void uv_kernel(const float* __restrict__ x,
                                                 const float* __restrict__ pos,
                                                 const float* __restrict__ W) {
    __shared__ __half sx[64 * 72];    //  9 KB
    __shared__ __half sW[128 * 72];   // 18 KB

    int tid  = threadIdx.x;
    int base = blockIdx.x * 64;

    // --- Stage W (combined + transposed-to-[oc][c], fp16). Coalesced reads.
#pragma unroll
    for (int j = 0; j < 16; ++j) {
        int i = tid + j * 256;
        int o = i >> 6, c = i & 63;
        float w1 = W[o * 128 + c];
        float w2 = W[o * 128 + 64 + c];
        sW[o * 72 + c]        = __float2half(w1 - w2);
        sW[(64 + o) * 72 + c] = __float2half(w2);
    }

    // --- Stage x tile: sx[nl][c] = fp16(x[b, c, n]). Coalesced reads over n.
#pragma unroll
    for (int j = 0; j < 16; ++j) {
        int i  = tid + j * 256;
        int c  = i >> 6, nl = i & 63;
        int node = base + nl;
        int b  = node / NPTS;
        int n  = node - b * NPTS;
        sx[nl * 72 + c] = __float2half(x[b * CC * NPTS + c * NPTS + n]);
    }

    // --- pos transpose by the first 64 threads.
    if (tid < 64) {
        int node = base + tid;
        int b = node / NPTS;
        int n = node - b * NPTS;
        const float* pb = pos + b * 3 * NPTS + n;
        float4 p;
        p.x = pb[0];
        p.y = pb[NPTS];
        p.z = pb[2 * NPTS];
        p.w = 0.0f;
        reinterpret_cast<float4*>(g_posT)[node] = p;
    }
    __syncthreads();

    int warp = tid >> 5;
    int lane = tid & 31;
    int m0   = (warp & 3) * 16;   // node row base within the 64-node tile
    int hsel = warp >> 2;         // 0 -> U (oc 0..63), 1 -> V (oc 64..127)
    int g    = lane >> 2;
    int t    = lane & 3;

    float acc[8][4];
#pragma unroll
    for (int nt = 0; nt < 8; ++nt)
#pragma unroll
        for (int r = 0; r < 4; ++r) acc[nt][r] = 0.0f;

    const __half* arow0 = sx + (m0 + g) * 72 + 2 * t;        // row g
    const __half* arow1 = sx + (m0 + g + 8) * 72 + 2 * t;    // row g+8
    const __half* brow  = sW + (hsel * 64 + g) * 72 + 2 * t; // n = g

#pragma unroll
    for (int k = 0; k < 4; ++k) {
        unsigned a0 = *reinterpret_cast<const unsigned*>(arow0 + 16 * k);
        unsigned a1 = *reinterpret_cast<const unsigned*>(arow1 + 16 * k);
        unsigned a2 = *reinterpret_cast<const unsigned*>(arow0 + 16 * k + 8);
        unsigned a3 = *reinterpret_cast<const unsigned*>(arow1 + 16 * k + 8);
#pragma unroll
        for (int nt = 0; nt < 8; ++nt) {
            unsigned b0 = *reinterpret_cast<const unsigned*>(brow + nt * 8 * 72 + 16 * k);
            unsigned b1 = *reinterpret_cast<const unsigned*>(brow + nt * 8 * 72 + 16 * k + 8);
            mma_16x8x16(acc[nt], a0, a1, a2, a3, b0, b1);
        }
    }

    // --- Epilogue: fp32 acc -> half2 -> global. Row = node, 32 half2 per row.
    unsigned* dstA = reinterpret_cast<unsigned*>(hsel ? g_V : g_U);
    int nlo = base + m0 + g;
#pragma unroll
    for (int nt = 0; nt < 8; ++nt) {
        dstA[nlo * 32 + nt * 4 + t]       = f2h2(acc[nt][0], acc[nt][1]);
        dstA[(nlo + 8) * 32 + nt * 4 + t] = f2h2(acc[nt][2], acc[nt][3]);
    }
}

// ---------------------------------------------------------------------------
// Kernel 2: per-edge combine + suppression + max over K — vectorized.
// (R9 version: single launch over both batches; that beat the split/stream
// variant by 6+ us.) Warp per point; lane (esub = lane>>3, q = lane&7) loads
// the q-th uint4 of edge (p*4+esub)'s U/V row; half2 epilogue; shfl-max.
// ---------------------------------------------------------------------------
__global__ __launch_bounds__(256) void edge_kernel(const int* __restrict__ ei,
                                                   const float* __restrict__ bias,
                                                   float* __restrict__ out) {
    __shared__ float    sm[8 * 66];   // output staging
    __shared__ unsigned ssh[8 * 16];  // suppression as half2(s,s), per warp/k
    __shared__ int      si[8 * 32];   // [warp][0..15: i1 (center), 16..31: i0]
    __shared__ unsigned sbias[32];    // bias as 32 half2

    int tid  = threadIdx.x;
    int warp = tid >> 5;
    int lane = tid & 31;

    if (tid < 32) {
        float2 bf = reinterpret_cast<const float2*>(bias)[tid];
        sbias[tid] = f2h2(bf.x, bf.y);
    }

    int g = blockIdx.x * 8 + warp;   // 20000 % 8 == 0 -> block never crosses batch
    int b = g / NPTS;
    int n = g - b * NPTS;

    const int* e0 = ei + (b * NPTS + n) * KK;                    // neighbor idx
    const int* e1 = ei + (BB * NPTS * KK) + (b * NPTS + n) * KK; // center idx

    const uint4*  Ub = g_U + b * NPTS * 8;
    const uint4*  Vb = g_V + b * NPTS * 8;
    const float4* Pb = reinterpret_cast<const float4*>(g_posT) + b * NPTS;

    if (lane < KK) {
        int i0 = e0[lane];
        int i1 = e1[lane];
        si[warp * 32 + lane]      = i1;
        si[warp * 32 + 16 + lane] = i0;
        float4 p1 = Pb[i1];
        float4 p0 = Pb[i0];
        float dx = p1.x - p0.x, dy = p1.y - p0.y, dz = p1.z - p0.z;
        float dis = sqrtf(dx * dx + dy * dy + dz * dz);
        float s = 2.0f / (1.0f + __expf(dis));   // 2*sigmoid(-dis)
        ssh[warp * 16 + lane] = f2h2(s, s);
    }
    __syncthreads();   // sbias (cross-warp) + si/ssh

    int esub = lane >> 3;    // which of 4 edges this pass
    int q    = lane & 7;     // which 16B quad of the 128B row

    uint4    u[4], v[4];
    unsigned sh[4];
#pragma unroll
    for (int p = 0; p < 4; ++p) {
        int k  = p * 4 + esub;
        int i1 = si[warp * 32 + k];
        int i0 = si[warp * 32 + 16 + k];
        u[p]  = Ub[i1 * 8 + q];
        v[p]  = Vb[i0 * 8 + q];
        sh[p] = ssh[warp * 16 + k];
    }

    uint4 bq = reinterpret_cast<const uint4*>(sbias)[q];  // bias for outputs 8q..8q+7
    __half2 b0 = u2h(bq.x), b1 = u2h(bq.y), b2 = u2h(bq.z), b3 = u2h(bq.w);

    const __half2 z = __floats2half2_rn(0.0f, 0.0f);
    __half2 a0 = z, a1 = z, a2 = z, a3 = z;   // relu * positive => >= 0

#pragma unroll
    for (int p = 0; p < 4; ++p) {
        __half2 s2 = u2h(sh[p]);
        a0 = __hmax2(a0, __hmul2(__hmax2(__hadd2(__hadd2(u2h(u[p].x), u2h(v[p].x)), b0), z), s2));
        a1 = __hmax2(a1, __hmul2(__hmax2(__hadd2(__hadd2(u2h(u[p].y), u2h(v[p].y)), b1), z), s2));
        a2 = __hmax2(a2, __hmul2(__hmax2(__hadd2(__hadd2(u2h(u[p].z), u2h(v[p].z)), b2), z), s2));
        a3 = __hmax2(a3, __hmul2(__hmax2(__hadd2(__hadd2(u2h(u[p].w), u2h(v[p].w)), b3), z), s2));
    }

    a0 = hmax2_xor(a0, 8);  a1 = hmax2_xor(a1, 8);
    a2 = hmax2_xor(a2, 8);  a3 = hmax2_xor(a3, 8);
    a0 = hmax2_xor(a0, 16); a1 = hmax2_xor(a1, 16);
    a2 = hmax2_xor(a2, 16); a3 = hmax2_xor(a3, 16);

    if (esub == 0) {   // lanes 0..7 write outputs 8q..8q+7 (float)
        float2* dst = reinterpret_cast<float2*>(sm + warp * 66 + q * 8);
        dst[0] = __half22float2(a0);
        dst[1] = __half22float2(a1);
        dst[2] = __half22float2(a2);
        dst[3] = __half22float2(a3);
    }
    __syncthreads();

    int base = blockIdx.x * 8;
    int ob = base / NPTS;               // batch of this block's points
    int on = base - ob * NPTS;          // first point index within batch
#pragma unroll
    for (int e = tid; e < CO * 8; e += 256) {
        int o  = e >> 3;
        int nn = e & 7;
        out[(ob * CO + o) * NPTS + on + nn] = sm[nn * 66 + o];
    }
}

extern "C" void kernel_launch(void* const* d_in, const int* in_sizes, int n_in,
                              void* d_out, int out_size) {
    const float* x    = (const float*)d_in[0];
    const int*   ei   = (const int*)d_in[1];
    const float* pos  = (const float*)d_in[2];
    const float* W    = (const float*)d_in[3];
    const float* bias = (const float*)d_in[4];
    float* out = (float*)d_out;

    uv_kernel<<<NODES / 64, 256>>>(x, pos, W);
    edge_kernel<<<NODES / 8, 256>>>(ei, bias, out);
}